// round 8
// baseline (speedup 1.0000x reference)
#include <cuda_runtime.h>
#include <cuda_bf16.h>
#include <stdint.h>
#include <math.h>

// Problem constants (fixed by the dataset)
#define BSZ   2
#define SEQL  2048
#define DM    1024
#define DI    2048      // d_inner
#define DS    16        // d_state
#define RNK   64        // dt_rank
#define XD    96        // dt_rank + 2*d_state
#define NCH   16        // number of scan chunks
#define CT    128       // chunk length (NCH*CT == SEQL)
#define ML    (BSZ*SEQL)  // 4096 rows

// ---------------- scratch (static __device__, no runtime alloc) ----------------
__device__ float g_xz    [ML * 2 * DI];
__device__ float g_xconv [ML * DI];
__device__ float g_xdbl  [ML * XD];
__device__ float g_delta [ML * DI];
__device__ float g_S     [ML * DI];
__device__ float g_ylocal[ML * DI];
__device__ float g_hend  [BSZ * NCH * DS * DI];
__device__ float g_hin   [BSZ * NCH * DS * DI];
__device__ float g_yfinal[ML * DI];
__device__ float g_Aneg  [DI * DS];

// split-bf16 operand buffers (ushort bit patterns)
__device__ unsigned short g_a1[ML * 3 * DM];        // hidden split   [4096 x 3072]
__device__ unsigned short g_b1[(2*DI) * 3 * DM];    // in_proj_w split[4096 x 3072]
__device__ unsigned short g_a2[ML * 3 * DI];        // yfinal split   [4096 x 6144]
__device__ unsigned short g_b2[DM * 3 * DI];        // out_proj_w split[1024 x 6144]

__device__ __forceinline__ float4 ld4(const float* p) {
    return *reinterpret_cast<const float4*>(p);
}
__device__ __forceinline__ float siluf(float x) {
    return x / (1.0f + __expf(-x));
}

// ---------------- split-bf16 conversion ----------------------------------------
// mode 0 (A operand): Y[M,3K] = [hi | hi | lo]
// mode 1 (B operand): Y[M,3K] = [hi | lo | hi]
// Together: A'.B' = hi.hi + hi.lo + lo.hi  (lo.lo dropped, ~2^-18 relative)
__global__ __launch_bounds__(256) void split_bf16_kernel(
    const float* __restrict__ X, unsigned short* __restrict__ Y,
    int K, int total, int mode)
{
    int idx = blockIdx.x * 256 + threadIdx.x;
    if (idx >= total) return;
    int m = idx / K;
    int k = idx - m * K;
    float x = X[idx];
    __nv_bfloat16 hi = __float2bfloat16(x);
    float lof = x - __bfloat162float(hi);
    __nv_bfloat16 lo = __float2bfloat16(lof);
    unsigned short hb = __bfloat16_as_ushort(hi);
    unsigned short lb = __bfloat16_as_ushort(lo);
    size_t base = (size_t)m * 3 * K;
    Y[base + k] = hb;
    if (mode == 0) {
        Y[base + K + k]     = hb;
        Y[base + 2 * K + k] = lb;
    } else {
        Y[base + K + k]     = lb;
        Y[base + 2 * K + k] = hb;
    }
}

// ---------------- bf16 HMMA GEMM: C[M,N] = A[M,K2] * B[N,K2]^T ------------------
// 256 threads (8 warps, 2 per SMSP). Templated BN: 256 (GEMM1) / 128 (GEMM2).
// Block tile 128 x BN x 32; warp tile 64 x BN/4; 3-stage cp.async pipeline.
#define TBK 32
#define SPAD 8
#define SLD  (TBK + SPAD)   // 40 ushorts per smem row
#define NSTAGE 3

__device__ __forceinline__ void cpasync16(unsigned int saddr, const void* gptr) {
    asm volatile("cp.async.cg.shared.global [%0], [%1], 16;\n" :: "r"(saddr), "l"(gptr));
}

template<int BN_>
__global__ __launch_bounds__(256) void gemm_bf16_mma(
    const unsigned short* __restrict__ A,   // [M][K2] bf16 bits
    const unsigned short* __restrict__ B,   // [N][K2] bf16 bits
    float* __restrict__ C, int ldc,
    int K2)
{
    constexpr int WN = BN_ / 4;       // warp N extent
    constexpr int NI = WN / 8;        // n-tiles per warp (8 or 4)
    constexpr int STAGE_USH = (128 + BN_) * SLD;

    extern __shared__ __align__(16) unsigned short smem_u[];

    const int tid  = threadIdx.x;
    const int lane = tid & 31;
    const int wid  = tid >> 5;
    const int wm   = (wid >> 2) * 64;          // warp M offset (0 or 64)
    const int wn   = (wid & 3) * WN;           // warp N offset
    const int row0 = blockIdx.y * 128;
    const int col0 = blockIdx.x * BN_;

    const int T = K2 / TBK;

    float acc[4][NI][4];
#pragma unroll
    for (int mi = 0; mi < 4; mi++)
#pragma unroll
        for (int ni = 0; ni < NI; ni++)
#pragma unroll
            for (int q = 0; q < 4; q++) acc[mi][ni][q] = 0.0f;

    auto issue = [&](int t) {
        int buf = t % NSTAGE;
        unsigned short* sa = smem_u + buf * STAGE_USH;
        unsigned short* sb = sa + 128 * SLD;
        int kk = t * TBK;
        // A: 128 rows x 32 cols = 512 x 16B vectors
#pragma unroll
        for (int i = 0; i < 2; i++) {
            int e = tid + 256 * i;
            int r = e >> 2;
            int c = e & 3;
            unsigned int s = (unsigned int)__cvta_generic_to_shared(&sa[r * SLD + c * 8]);
            cpasync16(s, A + (size_t)(row0 + r) * K2 + kk + c * 8);
        }
        // B: BN_ rows x 32 cols
#pragma unroll
        for (int i = 0; i < BN_ / 64; i++) {
            int e = tid + 256 * i;
            int r = e >> 2;
            int c = e & 3;
            unsigned int s = (unsigned int)__cvta_generic_to_shared(&sb[r * SLD + c * 8]);
            cpasync16(s, B + (size_t)(col0 + r) * K2 + kk + c * 8);
        }
        asm volatile("cp.async.commit_group;\n");
    };

    issue(0);
    if (T > 1) issue(1);

    for (int t = 0; t < T; t++) {
        if (t + 2 < T) issue(t + 2);
        // ensure chunk t complete
        int pend = T - 1 - t; if (pend > 2) pend = 2;
        if      (pend == 2) asm volatile("cp.async.wait_group 2;\n");
        else if (pend == 1) asm volatile("cp.async.wait_group 1;\n");
        else                asm volatile("cp.async.wait_group 0;\n");
        __syncthreads();

        const unsigned short* As = smem_u + (t % NSTAGE) * STAGE_USH;
        const unsigned short* Bs = As + 128 * SLD;

#pragma unroll
        for (int ks = 0; ks < 2; ks++) {
            const int kc = ks * 16 + (lane & 3) * 2;
            unsigned int af[4][4], bf[NI][2];
#pragma unroll
            for (int mi = 0; mi < 4; mi++) {
                int r = wm + mi * 16 + (lane >> 2);
                af[mi][0] = *(const unsigned int*)&As[r * SLD + kc];
                af[mi][1] = *(const unsigned int*)&As[(r + 8) * SLD + kc];
                af[mi][2] = *(const unsigned int*)&As[r * SLD + kc + 8];
                af[mi][3] = *(const unsigned int*)&As[(r + 8) * SLD + kc + 8];
            }
#pragma unroll
            for (int ni = 0; ni < NI; ni++) {
                int n = wn + ni * 8 + (lane >> 2);
                bf[ni][0] = *(const unsigned int*)&Bs[n * SLD + kc];
                bf[ni][1] = *(const unsigned int*)&Bs[n * SLD + kc + 8];
            }
#pragma unroll
            for (int mi = 0; mi < 4; mi++)
#pragma unroll
                for (int ni = 0; ni < NI; ni++) {
                    asm volatile(
                        "mma.sync.aligned.m16n8k16.row.col.f32.bf16.bf16.f32 "
                        "{%0,%1,%2,%3}, {%4,%5,%6,%7}, {%8,%9}, {%0,%1,%2,%3};"
                        : "+f"(acc[mi][ni][0]), "+f"(acc[mi][ni][1]),
                          "+f"(acc[mi][ni][2]), "+f"(acc[mi][ni][3])
                        : "r"(af[mi][0]), "r"(af[mi][1]), "r"(af[mi][2]), "r"(af[mi][3]),
                          "r"(bf[ni][0]), "r"(bf[ni][1]));
                }
        }
        __syncthreads();
    }

    // epilogue
#pragma unroll
    for (int mi = 0; mi < 4; mi++) {
        int r = row0 + wm + mi * 16 + (lane >> 2);
#pragma unroll
        for (int ni = 0; ni < NI; ni++) {
            int cn = col0 + wn + ni * 8 + (lane & 3) * 2;
            *(float2*)&C[(size_t)r * ldc + cn] =
                make_float2(acc[mi][ni][0], acc[mi][ni][1]);
            *(float2*)&C[(size_t)(r + 8) * ldc + cn] =
                make_float2(acc[mi][ni][2], acc[mi][ni][3]);
        }
    }
}

// ---------------- fp32 tiled SGEMM (kept for dt_proj, K=64) ---------------------
#define BM 128
#define BN 128
#define BKK 16

__global__ __launch_bounds__(256) void sgemm_tn(
    const float* __restrict__ A, int lda,
    const float* __restrict__ B, int ldb,
    float* __restrict__ C, int ldc,
    int M, int N, int K,
    const float* __restrict__ bias, int epi)
{
    __shared__ __align__(16) float As[BKK][BM + 4];
    __shared__ __align__(16) float Bs[BKK][BN + 4];

    const int tid = threadIdx.x;
    const int tx = tid & 15;
    const int ty = tid >> 4;
    const int row0 = blockIdx.y * BM;
    const int col0 = blockIdx.x * BN;

    const int lm = tid >> 1;
    const int lk = (tid & 1) * 8;

    float acc[8][8];
#pragma unroll
    for (int i = 0; i < 8; i++)
#pragma unroll
        for (int j = 0; j < 8; j++) acc[i][j] = 0.0f;

    for (int kk = 0; kk < K; kk += BKK) {
        {
            int gr = row0 + lm;
            float4 v0 = make_float4(0.f,0.f,0.f,0.f), v1 = v0;
            if (gr < M) {
                const float* p = A + (size_t)gr * lda + kk + lk;
                v0 = ld4(p); v1 = ld4(p + 4);
            }
            As[lk+0][lm] = v0.x; As[lk+1][lm] = v0.y;
            As[lk+2][lm] = v0.z; As[lk+3][lm] = v0.w;
            As[lk+4][lm] = v1.x; As[lk+5][lm] = v1.y;
            As[lk+6][lm] = v1.z; As[lk+7][lm] = v1.w;
        }
        {
            int gn = col0 + lm;
            float4 v0 = make_float4(0.f,0.f,0.f,0.f), v1 = v0;
            if (gn < N) {
                const float* p = B + (size_t)gn * ldb + kk + lk;
                v0 = ld4(p); v1 = ld4(p + 4);
            }
            Bs[lk+0][lm] = v0.x; Bs[lk+1][lm] = v0.y;
            Bs[lk+2][lm] = v0.z; Bs[lk+3][lm] = v0.w;
            Bs[lk+4][lm] = v1.x; Bs[lk+5][lm] = v1.y;
            Bs[lk+6][lm] = v1.z; Bs[lk+7][lm] = v1.w;
        }
        __syncthreads();

#pragma unroll
        for (int k = 0; k < BKK; k++) {
            float4 a0 = *reinterpret_cast<const float4*>(&As[k][ty*8]);
            float4 a1 = *reinterpret_cast<const float4*>(&As[k][ty*8+4]);
            float4 b0 = *reinterpret_cast<const float4*>(&Bs[k][tx*8]);
            float4 b1 = *reinterpret_cast<const float4*>(&Bs[k][tx*8+4]);
            float av[8] = {a0.x,a0.y,a0.z,a0.w,a1.x,a1.y,a1.z,a1.w};
            float bv[8] = {b0.x,b0.y,b0.z,b0.w,b1.x,b1.y,b1.z,b1.w};
#pragma unroll
            for (int i = 0; i < 8; i++)
#pragma unroll
                for (int j = 0; j < 8; j++)
                    acc[i][j] = fmaf(av[i], bv[j], acc[i][j]);
        }
        __syncthreads();
    }

#pragma unroll
    for (int i = 0; i < 8; i++) {
        int r = row0 + ty*8 + i;
        if (r >= M) continue;
#pragma unroll
        for (int j = 0; j < 8; j++) {
            int c = col0 + tx*8 + j;
            if (c >= N) continue;
            float v = acc[i][j];
            if (epi == 1) {
                v += bias[c];
                v = (v > 20.0f) ? v : log1pf(__expf(v));   // softplus
            }
            C[(size_t)r * ldc + c] = v;
        }
    }
}

// ---------------- depthwise causal conv (K=4) + bias + SiLU ---------------------
__global__ __launch_bounds__(256) void conv_silu_kernel(
    const float* __restrict__ conv_w,
    const float* __restrict__ conv_b)
{
    int d = blockIdx.x * 256 + threadIdx.x;
    int l = blockIdx.y;
    int b = blockIdx.z;
    float4 w = ld4(conv_w + d * 4);
    const float wv[4] = {w.x, w.y, w.z, w.w};
    float acc = conv_b[d];
    int base = b * SEQL;
#pragma unroll
    for (int k = 0; k < 4; k++) {
        int li = l - 3 + k;
        if (li >= 0)
            acc = fmaf(g_xz[(size_t)(base + li) * (2*DI) + d], wv[k], acc);
    }
    g_xconv[(size_t)(base + l) * DI + d] = siluf(acc);
}

// ---------------- x_proj GEMM: split-K x4 with atomic accumulation --------------
__global__ __launch_bounds__(256) void gemm_xdbl_splitk(
    const float* __restrict__ W)   // x_proj_w [96, 2048]
{
    __shared__ float As[32][33];
    __shared__ float Ws[96][33];
    int tid = threadIdx.x;
    int row0 = blockIdx.x * 32;
    int kq = blockIdx.y;           // 0..3, K chunk of 512
    int r = tid & 31;
    int g = tid >> 5;
    float acc[12];
#pragma unroll
    for (int j = 0; j < 12; j++) acc[j] = 0.0f;

    for (int kk = kq * 512; kk < (kq + 1) * 512; kk += 32) {
#pragma unroll
        for (int i = 0; i < 4; i++) {
            int e = tid + i * 256;
            int m = e >> 5, k = e & 31;
            As[m][k] = g_xconv[(size_t)(row0 + m) * DI + kk + k];
        }
#pragma unroll
        for (int i = 0; i < 12; i++) {
            int e = tid + i * 256;
            int n = e >> 5, k = e & 31;
            Ws[n][k] = W[(size_t)n * DI + kk + k];
        }
        __syncthreads();
#pragma unroll
        for (int k = 0; k < 32; k++) {
            float a = As[r][k];
#pragma unroll
            for (int j = 0; j < 12; j++)
                acc[j] = fmaf(a, Ws[g*12 + j][k], acc[j]);
        }
        __syncthreads();
    }
#pragma unroll
    for (int j = 0; j < 12; j++)
        atomicAdd(&g_xdbl[(size_t)(row0 + r) * XD + g*12 + j], acc[j]);
}

// ---------------- prep: Aneg = -exp(A_log) --------------------------------------
__global__ void prep_A_kernel(const float* __restrict__ A_log) {
    int i = blockIdx.x * 256 + threadIdx.x;
    if (i < DI * DS) g_Aneg[i] = -__expf(A_log[i]);
}

// ---------------- scan phase A: chunk-local scan (h0 = 0) -----------------------
__global__ __launch_bounds__(256) void scanA_kernel()
{
    int bc = blockIdx.x;
    int d     = (bc & 7) * 256 + threadIdx.x;
    int chunk = (bc >> 3) & 15;
    int b     = bc >> 7;

    float a[DS], h[DS];
#pragma unroll
    for (int n = 0; n < DS; n++) { a[n] = g_Aneg[d * DS + n]; h[n] = 0.0f; }
    float S = 0.0f;
    int l0 = chunk * CT;

    for (int t = 0; t < CT; t++) {
        size_t base = (size_t)(b * SEQL + l0 + t);
        float dlt = g_delta[base * DI + d];
        float u   = g_xconv[base * DI + d];
        S += dlt;
        g_S[base * DI + d] = S;
        float du = dlt * u;
        const float* bc_ptr = g_xdbl + base * XD + RNK;
        float4 B0 = ld4(bc_ptr), B1 = ld4(bc_ptr + 4);
        float4 B2 = ld4(bc_ptr + 8), B3 = ld4(bc_ptr + 12);
        float4 C0 = ld4(bc_ptr + 16), C1 = ld4(bc_ptr + 20);
        float4 C2 = ld4(bc_ptr + 24), C3 = ld4(bc_ptr + 28);
        float Bv[DS] = {B0.x,B0.y,B0.z,B0.w,B1.x,B1.y,B1.z,B1.w,
                        B2.x,B2.y,B2.z,B2.w,B3.x,B3.y,B3.z,B3.w};
        float Cv[DS] = {C0.x,C0.y,C0.z,C0.w,C1.x,C1.y,C1.z,C1.w,
                        C2.x,C2.y,C2.z,C2.w,C3.x,C3.y,C3.z,C3.w};
        float y = 0.0f;
#pragma unroll
        for (int n = 0; n < DS; n++) {
            float dA = __expf(a[n] * dlt);
            h[n] = fmaf(h[n], dA, du * Bv[n]);
            y = fmaf(h[n], Cv[n], y);
        }
        g_ylocal[base * DI + d] = y;
    }
#pragma unroll
    for (int n = 0; n < DS; n++)
        g_hend[((size_t)(b * NCH + chunk) * DS + n) * DI + d] = h[n];
}

// ---------------- scan phase B: cross-chunk prefix (16 steps) -------------------
__global__ __launch_bounds__(256) void scanB_kernel()
{
    int bc = blockIdx.x;
    int d = (bc & 7) * 256 + threadIdx.x;
    int n = (bc >> 3) & 15;
    int b = bc >> 7;
    float an = g_Aneg[d * DS + n];
    float hin = 0.0f;
    for (int c = 0; c < NCH; c++) {
        size_t idx = ((size_t)(b * NCH + c) * DS + n) * DI + d;
        g_hin[idx] = hin;
        float Sc = g_S[(size_t)(b * SEQL + c * CT + CT - 1) * DI + d];
        hin = fmaf(hin, __expf(an * Sc), g_hend[idx]);
    }
}

// ---------------- scan phase C: correction + D*x + silu(z) gate -----------------
__global__ __launch_bounds__(256) void scanC_kernel(const float* __restrict__ Dp)
{
    int d = blockIdx.x * 256 + threadIdx.x;
    int l = blockIdx.y;
    int b = blockIdx.z;
    size_t base = (size_t)(b * SEQL + l);
    int chunk = l >> 7;

    float S = g_S[base * DI + d];
    float y = g_ylocal[base * DI + d];
    const float* cp = g_xdbl + base * XD + RNK + DS;
    float4 C0 = ld4(cp), C1 = ld4(cp + 4), C2 = ld4(cp + 8), C3 = ld4(cp + 12);
    float Cv[DS] = {C0.x,C0.y,C0.z,C0.w,C1.x,C1.y,C1.z,C1.w,
                    C2.x,C2.y,C2.z,C2.w,C3.x,C3.y,C3.z,C3.w};
#pragma unroll
    for (int n = 0; n < DS; n++) {
        float an = g_Aneg[d * DS + n];
        float hin = g_hin[((size_t)(b * NCH + chunk) * DS + n) * DI + d];
        y = fmaf(Cv[n] * __expf(an * S), hin, y);
    }
    float x = g_xconv[base * DI + d];
    float z = g_xz[base * (2*DI) + DI + d];
    y = fmaf(Dp[d], x, y);
    g_yfinal[base * DI + d] = y * siluf(z);
}

// ---------------- launch --------------------------------------------------------
extern "C" void kernel_launch(void* const* d_in, const int* in_sizes, int n_in,
                              void* d_out, int out_size)
{
    const float* hidden    = (const float*)d_in[0];   // [2,2048,1024]
    const float* in_proj_w = (const float*)d_in[1];   // [4096,1024]
    const float* conv_w    = (const float*)d_in[2];   // [2048,1,4]
    const float* conv_b    = (const float*)d_in[3];   // [2048]
    const float* x_proj_w  = (const float*)d_in[4];   // [96,2048]
    const float* dt_proj_w = (const float*)d_in[5];   // [2048,64]
    const float* dt_proj_b = (const float*)d_in[6];   // [2048]
    const float* A_log     = (const float*)d_in[7];   // [2048,16]
    const float* Dp        = (const float*)d_in[8];   // [2048]
    const float* out_proj_w= (const float*)d_in[9];   // [1024,2048]
    float* out = (float*)d_out;                       // [2,2048,1024]

    float* xz     = nullptr; cudaGetSymbolAddress((void**)&xz,     g_xz);
    float* xdbl   = nullptr; cudaGetSymbolAddress((void**)&xdbl,   g_xdbl);
    float* delta  = nullptr; cudaGetSymbolAddress((void**)&delta,  g_delta);
    float* yfinal = nullptr; cudaGetSymbolAddress((void**)&yfinal, g_yfinal);
    unsigned short* a1 = nullptr; cudaGetSymbolAddress((void**)&a1, g_a1);
    unsigned short* b1 = nullptr; cudaGetSymbolAddress((void**)&b1, g_b1);
    unsigned short* a2 = nullptr; cudaGetSymbolAddress((void**)&a2, g_a2);
    unsigned short* b2 = nullptr; cudaGetSymbolAddress((void**)&b2, g_b2);

    // dynamic smem sizes: (128+BN)*SLD*2 bytes * NSTAGE
    const int smem1 = (128 + 256) * SLD * 2 * NSTAGE;   // 92160
    const int smem2 = (128 + 128) * SLD * 2 * NSTAGE;   // 61440
    cudaFuncSetAttribute(gemm_bf16_mma<256>,
                         cudaFuncAttributeMaxDynamicSharedMemorySize, smem1);
    cudaFuncSetAttribute(gemm_bf16_mma<128>,
                         cudaFuncAttributeMaxDynamicSharedMemorySize, smem2);

    // 0) split-bf16 conversions for GEMM1 (A: [hi|hi|lo], B: [hi|lo|hi])
    {
        int tot = ML * DM;
        split_bf16_kernel<<<(tot + 255)/256, 256>>>(hidden, a1, DM, tot, 0);
        tot = (2*DI) * DM;
        split_bf16_kernel<<<(tot + 255)/256, 256>>>(in_proj_w, b1, DM, tot, 1);
    }
    // 1) xz = hidden @ in_proj_w^T  (HMMA, K2 = 3*1024, tile 128x256)
    gemm_bf16_mma<256><<<dim3((2*DI)/256, ML/128), 256, smem1>>>(
        a1, b1, xz, 2*DI, 3*DM);
    // 2) depthwise conv + silu
    conv_silu_kernel<<<dim3(DI/256, SEQL, BSZ), 256>>>(conv_w, conv_b);
    // 3) Aneg = -exp(A_log)
    prep_A_kernel<<<(DI*DS + 255)/256, 256>>>(A_log);
    // 4) x_dbl = xconv @ x_proj_w^T  (split-K x4 + atomics)
    cudaMemsetAsync(xdbl, 0, (size_t)ML * XD * sizeof(float));
    gemm_xdbl_splitk<<<dim3(ML/32, 4), 256>>>(x_proj_w);
    // 5) delta = softplus(x_dbl[:, :64] @ dt_proj_w^T + b)
    sgemm_tn<<<dim3(DI/BN, ML/BM), 256>>>(xdbl, XD, dt_proj_w, RNK,
                                          delta, DI, ML, DI, RNK, dt_proj_b, 1);
    // 6) chunked selective scan
    scanA_kernel<<<BSZ*NCH*(DI/256), 256>>>();
    scanB_kernel<<<BSZ*DS*(DI/256), 256>>>();
    scanC_kernel<<<dim3(DI/256, SEQL, BSZ), 256>>>(Dp);
    // 7) split-bf16 conversions for GEMM_out (A: [hi|hi|lo], B: [hi|lo|hi])
    {
        int tot = ML * DI;
        split_bf16_kernel<<<(tot + 255)/256, 256>>>(yfinal, a2, DI, tot, 0);
        tot = DM * DI;
        split_bf16_kernel<<<(tot + 255)/256, 256>>>(out_proj_w, b2, DI, tot, 1);
    }
    // 8) out = yfinal @ out_proj_w^T  (HMMA, K2 = 3*2048, tile 128x128)
    gemm_bf16_mma<128><<<dim3(DM/128, ML/128), 256, smem2>>>(
        a2, b2, out, DM, 3*DI);
}

// round 10
// speedup vs baseline: 1.6913x; 1.6913x over previous
#include <cuda_runtime.h>
#include <cuda_bf16.h>
#include <stdint.h>
#include <math.h>

// Problem constants (fixed by the dataset)
#define BSZ   2
#define SEQL  2048
#define DM    1024
#define DI    2048      // d_inner
#define DS    16        // d_state
#define RNK   64        // dt_rank
#define XD    96        // dt_rank + 2*d_state
#define NCH   16        // number of scan chunks
#define CT    128       // chunk length (NCH*CT == SEQL)
#define ML    (BSZ*SEQL)  // 4096 rows

// ---------------- scratch (static __device__, no runtime alloc) ----------------
__device__ float g_xz    [ML * 2 * DI];
__device__ float g_xconv [ML * DI];
__device__ float g_xdbl  [ML * XD];
__device__ float g_delta [ML * DI];
__device__ float g_S     [ML * DI];
__device__ float g_ylocal[ML * DI];
__device__ float g_hend  [BSZ * NCH * DS * DI];
__device__ float g_hin   [BSZ * NCH * DS * DI];
__device__ float g_Aneg  [DI * DS];

// split-bf16 operand buffers (ushort bit patterns)
__device__ unsigned short g_a1[ML * 3 * DM];        // hidden split   [4096 x 3072]
__device__ unsigned short g_b1[(2*DI) * 3 * DM];    // in_proj_w split[4096 x 3072]
__device__ unsigned short g_a2[ML * 3 * DI];        // yfinal split   [4096 x 6144]
__device__ unsigned short g_b2[DM * 3 * DI];        // out_proj_w split[1024 x 6144]

__device__ __forceinline__ float4 ld4(const float* p) {
    return *reinterpret_cast<const float4*>(p);
}
__device__ __forceinline__ float siluf(float x) {
    return x / (1.0f + __expf(-x));
}
__device__ __forceinline__ void split1(float x, unsigned short& hb, unsigned short& lb) {
    __nv_bfloat16 hi = __float2bfloat16(x);
    float lof = x - __bfloat162float(hi);
    __nv_bfloat16 lo = __float2bfloat16(lof);
    hb = __bfloat16_as_ushort(hi);
    lb = __bfloat16_as_ushort(lo);
}

// ---------------- split-bf16 conversion (vectorized, 4 elems/thread) ------------
// mode 0 (A operand): Y[M,3K] = [hi | hi | lo]
// mode 1 (B operand): Y[M,3K] = [hi | lo | hi]
// Together: A'.B' = hi.hi + hi.lo + lo.hi  (lo.lo dropped, ~2^-18 relative)
__global__ __launch_bounds__(256) void split_bf16_kernel(
    const float* __restrict__ X, unsigned short* __restrict__ Y,
    int K, int total4, int mode)
{
    int idx4 = blockIdx.x * 256 + threadIdx.x;
    if (idx4 >= total4) return;
    int idx = idx4 * 4;                 // K is a multiple of 4
    int m = idx / K;
    int k = idx - m * K;
    float4 v = ld4(X + idx);
    unsigned short hb[4], lb[4];
    split1(v.x, hb[0], lb[0]); split1(v.y, hb[1], lb[1]);
    split1(v.z, hb[2], lb[2]); split1(v.w, hb[3], lb[3]);
    size_t base = (size_t)m * 3 * K + k;
    ushort4 H = make_ushort4(hb[0], hb[1], hb[2], hb[3]);
    ushort4 L = make_ushort4(lb[0], lb[1], lb[2], lb[3]);
    *reinterpret_cast<ushort4*>(Y + base) = H;
    if (mode == 0) {
        *reinterpret_cast<ushort4*>(Y + base + K)     = H;
        *reinterpret_cast<ushort4*>(Y + base + 2 * K) = L;
    } else {
        *reinterpret_cast<ushort4*>(Y + base + K)     = L;
        *reinterpret_cast<ushort4*>(Y + base + 2 * K) = H;
    }
}

// ---------------- bf16 tensor-core GEMM (R5-proven): C = A[M,K2] * B[N,K2]^T ----
// 128x128x32 block tile, 128 threads, 4 warps of 64x64, cp.async double buffer.
#define TBK 32
#define SPAD 8
#define SLD  (TBK + SPAD)   // 40 elements per smem row

__device__ __forceinline__ void cpasync16(unsigned int saddr, const void* gptr) {
    asm volatile("cp.async.cg.shared.global [%0], [%1], 16;\n" :: "r"(saddr), "l"(gptr));
}

__global__ __launch_bounds__(128) void gemm_bf16_split(
    const unsigned short* __restrict__ A,   // [M][K2] bf16 bits
    const unsigned short* __restrict__ B,   // [N][K2] bf16 bits
    float* __restrict__ C, int ldc,
    int K2)
{
    __shared__ __align__(16) unsigned short sm[2][2][128][SLD];

    const int tid  = threadIdx.x;
    const int lane = tid & 31;
    const int wid  = tid >> 5;
    const int wm   = (wid >> 1) * 64;    // warp M offset
    const int wn   = (wid & 1) * 64;     // warp N offset
    const int row0 = blockIdx.y * 128;
    const int col0 = blockIdx.x * 128;

    const int T = K2 / TBK;

    float acc[4][8][4];
#pragma unroll
    for (int mi = 0; mi < 4; mi++)
#pragma unroll
        for (int ni = 0; ni < 8; ni++)
#pragma unroll
            for (int q = 0; q < 4; q++) acc[mi][ni][q] = 0.0f;

    auto issue = [&](int t, int buf) {
        int kk = t * TBK;
#pragma unroll
        for (int i = 0; i < 4; i++) {
            int e = tid + 128 * i;
            int r = e >> 2;
            int c = e & 3;
            unsigned int sa = (unsigned int)__cvta_generic_to_shared(&sm[buf][0][r][c * 8]);
            cpasync16(sa, A + (size_t)(row0 + r) * K2 + kk + c * 8);
            unsigned int sb = (unsigned int)__cvta_generic_to_shared(&sm[buf][1][r][c * 8]);
            cpasync16(sb, B + (size_t)(col0 + r) * K2 + kk + c * 8);
        }
        asm volatile("cp.async.commit_group;\n");
    };

    issue(0, 0);

    for (int t = 0; t < T; t++) {
        if (t + 1 < T) {
            issue(t + 1, (t + 1) & 1);
            asm volatile("cp.async.wait_group 1;\n");
        } else {
            asm volatile("cp.async.wait_group 0;\n");
        }
        __syncthreads();

        const unsigned short (*As)[SLD] = sm[t & 1][0];
        const unsigned short (*Bs)[SLD] = sm[t & 1][1];

#pragma unroll
        for (int ks = 0; ks < 2; ks++) {
            const int kc = ks * 16 + (lane & 3) * 2;
            unsigned int af[4][4], bf[8][2];
#pragma unroll
            for (int mi = 0; mi < 4; mi++) {
                int r = wm + mi * 16 + (lane >> 2);
                af[mi][0] = *(const unsigned int*)&As[r][kc];
                af[mi][1] = *(const unsigned int*)&As[r + 8][kc];
                af[mi][2] = *(const unsigned int*)&As[r][kc + 8];
                af[mi][3] = *(const unsigned int*)&As[r + 8][kc + 8];
            }
#pragma unroll
            for (int ni = 0; ni < 8; ni++) {
                int n = wn + ni * 8 + (lane >> 2);
                bf[ni][0] = *(const unsigned int*)&Bs[n][kc];
                bf[ni][1] = *(const unsigned int*)&Bs[n][kc + 8];
            }
#pragma unroll
            for (int mi = 0; mi < 4; mi++)
#pragma unroll
                for (int ni = 0; ni < 8; ni++) {
                    asm volatile(
                        "mma.sync.aligned.m16n8k16.row.col.f32.bf16.bf16.f32 "
                        "{%0,%1,%2,%3}, {%4,%5,%6,%7}, {%8,%9}, {%0,%1,%2,%3};"
                        : "+f"(acc[mi][ni][0]), "+f"(acc[mi][ni][1]),
                          "+f"(acc[mi][ni][2]), "+f"(acc[mi][ni][3])
                        : "r"(af[mi][0]), "r"(af[mi][1]), "r"(af[mi][2]), "r"(af[mi][3]),
                          "r"(bf[ni][0]), "r"(bf[ni][1]));
                }
        }
        __syncthreads();
    }

    // epilogue
#pragma unroll
    for (int mi = 0; mi < 4; mi++) {
        int r = row0 + wm + mi * 16 + (lane >> 2);
#pragma unroll
        for (int ni = 0; ni < 8; ni++) {
            int cn = col0 + wn + ni * 8 + (lane & 3) * 2;
            *(float2*)&C[(size_t)r * ldc + cn] =
                make_float2(acc[mi][ni][0], acc[mi][ni][1]);
            *(float2*)&C[(size_t)(r + 8) * ldc + cn] =
                make_float2(acc[mi][ni][2], acc[mi][ni][3]);
        }
    }
}

// ---------------- fp32 tiled SGEMM (kept for dt_proj, K=64) ---------------------
#define BM 128
#define BN 128
#define BKK 16

__global__ __launch_bounds__(256) void sgemm_tn(
    const float* __restrict__ A, int lda,
    const float* __restrict__ B, int ldb,
    float* __restrict__ C, int ldc,
    int M, int N, int K,
    const float* __restrict__ bias, int epi)
{
    __shared__ __align__(16) float As[BKK][BM + 4];
    __shared__ __align__(16) float Bs[BKK][BN + 4];

    const int tid = threadIdx.x;
    const int tx = tid & 15;
    const int ty = tid >> 4;
    const int row0 = blockIdx.y * BM;
    const int col0 = blockIdx.x * BN;

    const int lm = tid >> 1;
    const int lk = (tid & 1) * 8;

    float acc[8][8];
#pragma unroll
    for (int i = 0; i < 8; i++)
#pragma unroll
        for (int j = 0; j < 8; j++) acc[i][j] = 0.0f;

    for (int kk = 0; kk < K; kk += BKK) {
        {
            int gr = row0 + lm;
            float4 v0 = make_float4(0.f,0.f,0.f,0.f), v1 = v0;
            if (gr < M) {
                const float* p = A + (size_t)gr * lda + kk + lk;
                v0 = ld4(p); v1 = ld4(p + 4);
            }
            As[lk+0][lm] = v0.x; As[lk+1][lm] = v0.y;
            As[lk+2][lm] = v0.z; As[lk+3][lm] = v0.w;
            As[lk+4][lm] = v1.x; As[lk+5][lm] = v1.y;
            As[lk+6][lm] = v1.z; As[lk+7][lm] = v1.w;
        }
        {
            int gn = col0 + lm;
            float4 v0 = make_float4(0.f,0.f,0.f,0.f), v1 = v0;
            if (gn < N) {
                const float* p = B + (size_t)gn * ldb + kk + lk;
                v0 = ld4(p); v1 = ld4(p + 4);
            }
            Bs[lk+0][lm] = v0.x; Bs[lk+1][lm] = v0.y;
            Bs[lk+2][lm] = v0.z; Bs[lk+3][lm] = v0.w;
            Bs[lk+4][lm] = v1.x; Bs[lk+5][lm] = v1.y;
            Bs[lk+6][lm] = v1.z; Bs[lk+7][lm] = v1.w;
        }
        __syncthreads();

#pragma unroll
        for (int k = 0; k < BKK; k++) {
            float4 a0 = *reinterpret_cast<const float4*>(&As[k][ty*8]);
            float4 a1 = *reinterpret_cast<const float4*>(&As[k][ty*8+4]);
            float4 b0 = *reinterpret_cast<const float4*>(&Bs[k][tx*8]);
            float4 b1 = *reinterpret_cast<const float4*>(&Bs[k][tx*8+4]);
            float av[8] = {a0.x,a0.y,a0.z,a0.w,a1.x,a1.y,a1.z,a1.w};
            float bv[8] = {b0.x,b0.y,b0.z,b0.w,b1.x,b1.y,b1.z,b1.w};
#pragma unroll
            for (int i = 0; i < 8; i++)
#pragma unroll
                for (int j = 0; j < 8; j++)
                    acc[i][j] = fmaf(av[i], bv[j], acc[i][j]);
        }
        __syncthreads();
    }

#pragma unroll
    for (int i = 0; i < 8; i++) {
        int r = row0 + ty*8 + i;
        if (r >= M) continue;
#pragma unroll
        for (int j = 0; j < 8; j++) {
            int c = col0 + tx*8 + j;
            if (c >= N) continue;
            float v = acc[i][j];
            if (epi == 1) {
                v += bias[c];
                v = (v > 20.0f) ? v : log1pf(__expf(v));   // softplus
            }
            C[(size_t)r * ldc + c] = v;
        }
    }
}

// ---------------- depthwise causal conv (K=4) + bias + SiLU ---------------------
__global__ __launch_bounds__(256) void conv_silu_kernel(
    const float* __restrict__ conv_w,
    const float* __restrict__ conv_b)
{
    int d = blockIdx.x * 256 + threadIdx.x;
    int l = blockIdx.y;
    int b = blockIdx.z;
    float4 w = ld4(conv_w + d * 4);
    const float wv[4] = {w.x, w.y, w.z, w.w};
    float acc = conv_b[d];
    int base = b * SEQL;
#pragma unroll
    for (int k = 0; k < 4; k++) {
        int li = l - 3 + k;
        if (li >= 0)
            acc = fmaf(g_xz[(size_t)(base + li) * (2*DI) + d], wv[k], acc);
    }
    g_xconv[(size_t)(base + l) * DI + d] = siluf(acc);
}

// ---------------- x_proj GEMM: split-K x8 with atomic accumulation --------------
__global__ __launch_bounds__(256) void gemm_xdbl_splitk(
    const float* __restrict__ W)   // x_proj_w [96, 2048]
{
    __shared__ float As[32][33];
    __shared__ float Ws[96][33];
    int tid = threadIdx.x;
    int row0 = blockIdx.x * 32;
    int kq = blockIdx.y;           // 0..7, K chunk of 256
    int r = tid & 31;
    int g = tid >> 5;
    float acc[12];
#pragma unroll
    for (int j = 0; j < 12; j++) acc[j] = 0.0f;

    for (int kk = kq * 256; kk < (kq + 1) * 256; kk += 32) {
#pragma unroll
        for (int i = 0; i < 4; i++) {
            int e = tid + i * 256;
            int m = e >> 5, k = e & 31;
            As[m][k] = g_xconv[(size_t)(row0 + m) * DI + kk + k];
        }
#pragma unroll
        for (int i = 0; i < 12; i++) {
            int e = tid + i * 256;
            int n = e >> 5, k = e & 31;
            Ws[n][k] = W[(size_t)n * DI + kk + k];
        }
        __syncthreads();
#pragma unroll
        for (int k = 0; k < 32; k++) {
            float a = As[r][k];
#pragma unroll
            for (int j = 0; j < 12; j++)
                acc[j] = fmaf(a, Ws[g*12 + j][k], acc[j]);
        }
        __syncthreads();
    }
#pragma unroll
    for (int j = 0; j < 12; j++)
        atomicAdd(&g_xdbl[(size_t)(row0 + r) * XD + g*12 + j], acc[j]);
}

// ---------------- prep: Aneg = -exp(A_log) --------------------------------------
__global__ void prep_A_kernel(const float* __restrict__ A_log) {
    int i = blockIdx.x * 256 + threadIdx.x;
    if (i < DI * DS) g_Aneg[i] = -__expf(A_log[i]);
}

// ---------------- scan phase A: chunk-local scan (h0 = 0) -----------------------
__global__ __launch_bounds__(256) void scanA_kernel()
{
    int bc = blockIdx.x;
    int d     = (bc & 7) * 256 + threadIdx.x;
    int chunk = (bc >> 3) & 15;
    int b     = bc >> 7;

    float a[DS], h[DS];
#pragma unroll
    for (int n = 0; n < DS; n++) { a[n] = g_Aneg[d * DS + n]; h[n] = 0.0f; }
    float S = 0.0f;
    int l0 = chunk * CT;

    for (int t = 0; t < CT; t++) {
        size_t base = (size_t)(b * SEQL + l0 + t);
        float dlt = g_delta[base * DI + d];
        float u   = g_xconv[base * DI + d];
        S += dlt;
        g_S[base * DI + d] = S;
        float du = dlt * u;
        const float* bc_ptr = g_xdbl + base * XD + RNK;
        float4 B0 = ld4(bc_ptr), B1 = ld4(bc_ptr + 4);
        float4 B2 = ld4(bc_ptr + 8), B3 = ld4(bc_ptr + 12);
        float4 C0 = ld4(bc_ptr + 16), C1 = ld4(bc_ptr + 20);
        float4 C2 = ld4(bc_ptr + 24), C3 = ld4(bc_ptr + 28);
        float Bv[DS] = {B0.x,B0.y,B0.z,B0.w,B1.x,B1.y,B1.z,B1.w,
                        B2.x,B2.y,B2.z,B2.w,B3.x,B3.y,B3.z,B3.w};
        float Cv[DS] = {C0.x,C0.y,C0.z,C0.w,C1.x,C1.y,C1.z,C1.w,
                        C2.x,C2.y,C2.z,C2.w,C3.x,C3.y,C3.z,C3.w};
        float y = 0.0f;
#pragma unroll
        for (int n = 0; n < DS; n++) {
            float dA = __expf(a[n] * dlt);
            h[n] = fmaf(h[n], dA, du * Bv[n]);
            y = fmaf(h[n], Cv[n], y);
        }
        g_ylocal[base * DI + d] = y;
    }
#pragma unroll
    for (int n = 0; n < DS; n++)
        g_hend[((size_t)(b * NCH + chunk) * DS + n) * DI + d] = h[n];
}

// ---------------- scan phase B: cross-chunk prefix (16 steps) -------------------
__global__ __launch_bounds__(256) void scanB_kernel()
{
    int bc = blockIdx.x;
    int d = (bc & 7) * 256 + threadIdx.x;
    int n = (bc >> 3) & 15;
    int b = bc >> 7;
    float an = g_Aneg[d * DS + n];
    float hin = 0.0f;
    for (int c = 0; c < NCH; c++) {
        size_t idx = ((size_t)(b * NCH + c) * DS + n) * DI + d;
        g_hin[idx] = hin;
        float Sc = g_S[(size_t)(b * SEQL + c * CT + CT - 1) * DI + d];
        hin = fmaf(hin, __expf(an * Sc), g_hend[idx]);
    }
}

// ---------------- scan phase C: correction + D*x + silu(z) gate + bf16 split ----
// Writes the GEMM2 A-operand (g_a2, mode-0 split [hi|hi|lo]) directly.
__global__ __launch_bounds__(256) void scanC_kernel(const float* __restrict__ Dp)
{
    int d = blockIdx.x * 256 + threadIdx.x;
    int l = blockIdx.y;
    int b = blockIdx.z;
    size_t base = (size_t)(b * SEQL + l);
    int chunk = l >> 7;

    float S = g_S[base * DI + d];
    float y = g_ylocal[base * DI + d];
    const float* cp = g_xdbl + base * XD + RNK + DS;
    float4 C0 = ld4(cp), C1 = ld4(cp + 4), C2 = ld4(cp + 8), C3 = ld4(cp + 12);
    float Cv[DS] = {C0.x,C0.y,C0.z,C0.w,C1.x,C1.y,C1.z,C1.w,
                    C2.x,C2.y,C2.z,C2.w,C3.x,C3.y,C3.z,C3.w};
#pragma unroll
    for (int n = 0; n < DS; n++) {
        float an = g_Aneg[d * DS + n];
        float hin = g_hin[((size_t)(b * NCH + chunk) * DS + n) * DI + d];
        y = fmaf(Cv[n] * __expf(an * S), hin, y);
    }
    float x = g_xconv[base * DI + d];
    float z = g_xz[base * (2*DI) + DI + d];
    y = fmaf(Dp[d], x, y);
    y = y * siluf(z);

    // fused mode-0 split-bf16 write of the GEMM2 A operand
    unsigned short hb, lb;
    split1(y, hb, lb);
    size_t ob = base * (3 * DI) + d;
    g_a2[ob]          = hb;
    g_a2[ob + DI]     = hb;
    g_a2[ob + 2 * DI] = lb;
}

// ---------------- launch --------------------------------------------------------
extern "C" void kernel_launch(void* const* d_in, const int* in_sizes, int n_in,
                              void* d_out, int out_size)
{
    const float* hidden    = (const float*)d_in[0];   // [2,2048,1024]
    const float* in_proj_w = (const float*)d_in[1];   // [4096,1024]
    const float* conv_w    = (const float*)d_in[2];   // [2048,1,4]
    const float* conv_b    = (const float*)d_in[3];   // [2048]
    const float* x_proj_w  = (const float*)d_in[4];   // [96,2048]
    const float* dt_proj_w = (const float*)d_in[5];   // [2048,64]
    const float* dt_proj_b = (const float*)d_in[6];   // [2048]
    const float* A_log     = (const float*)d_in[7];   // [2048,16]
    const float* Dp        = (const float*)d_in[8];   // [2048]
    const float* out_proj_w= (const float*)d_in[9];   // [1024,2048]
    float* out = (float*)d_out;                       // [2,2048,1024]

    float* xz     = nullptr; cudaGetSymbolAddress((void**)&xz,     g_xz);
    float* xdbl   = nullptr; cudaGetSymbolAddress((void**)&xdbl,   g_xdbl);
    float* delta  = nullptr; cudaGetSymbolAddress((void**)&delta,  g_delta);
    unsigned short* a1 = nullptr; cudaGetSymbolAddress((void**)&a1, g_a1);
    unsigned short* b1 = nullptr; cudaGetSymbolAddress((void**)&b1, g_b1);
    unsigned short* a2 = nullptr; cudaGetSymbolAddress((void**)&a2, g_a2);
    unsigned short* b2 = nullptr; cudaGetSymbolAddress((void**)&b2, g_b2);

    // 0) split-bf16 conversions for GEMM1 (A: [hi|hi|lo], B: [hi|lo|hi])
    {
        int tot4 = (ML * DM) / 4;
        split_bf16_kernel<<<(tot4 + 255)/256, 256>>>(hidden, a1, DM, tot4, 0);
        tot4 = ((2*DI) * DM) / 4;
        split_bf16_kernel<<<(tot4 + 255)/256, 256>>>(in_proj_w, b1, DM, tot4, 1);
    }
    // 1) xz = hidden @ in_proj_w^T  (HMMA split-bf16, K2 = 3*1024)
    gemm_bf16_split<<<dim3((2*DI)/128, ML/128), 128>>>(a1, b1, xz, 2*DI, 3*DM);
    // 2) depthwise conv + silu
    conv_silu_kernel<<<dim3(DI/256, SEQL, BSZ), 256>>>(conv_w, conv_b);
    // 3) Aneg = -exp(A_log)
    prep_A_kernel<<<(DI*DS + 255)/256, 256>>>(A_log);
    // 4) x_dbl = xconv @ x_proj_w^T  (split-K x8 + atomics)
    cudaMemsetAsync(xdbl, 0, (size_t)ML * XD * sizeof(float));
    gemm_xdbl_splitk<<<dim3(ML/32, 8), 256>>>(x_proj_w);
    // 5) delta = softplus(x_dbl[:, :64] @ dt_proj_w^T + b)
    sgemm_tn<<<dim3(DI/BN, ML/BM), 256>>>(xdbl, XD, dt_proj_w, RNK,
                                          delta, DI, ML, DI, RNK, dt_proj_b, 1);
    // 6) chunked selective scan (scanC fuses the GEMM2 A-operand split)
    scanA_kernel<<<BSZ*NCH*(DI/256), 256>>>();
    scanB_kernel<<<BSZ*DS*(DI/256), 256>>>();
    scanC_kernel<<<dim3(DI/256, SEQL, BSZ), 256>>>(Dp);
    // 7) split-bf16 conversion for GEMM2 B operand
    {
        int tot4 = (DM * DI) / 4;
        split_bf16_kernel<<<(tot4 + 255)/256, 256>>>(out_proj_w, b2, DI, tot4, 1);
    }
    // 8) out = yfinal @ out_proj_w^T  (HMMA split-bf16, K2 = 3*2048)
    gemm_bf16_split<<<dim3(DM/128, ML/128), 128>>>(a2, b2, out, DM, 3*DI);
}

// round 11
// speedup vs baseline: 1.8127x; 1.0718x over previous
#include <cuda_runtime.h>
#include <cuda_bf16.h>
#include <stdint.h>
#include <math.h>

// Problem constants (fixed by the dataset)
#define BSZ   2
#define SEQL  2048
#define DM    1024
#define DI    2048      // d_inner
#define DS    16        // d_state
#define RNK   64        // dt_rank
#define XD    96        // dt_rank + 2*d_state
#define NCH   16        // number of scan chunks
#define CT    128       // chunk length (NCH*CT == SEQL)
#define ML    (BSZ*SEQL)  // 4096 rows

// ---------------- scratch (static __device__, no runtime alloc) ----------------
__device__ float g_xz    [ML * 2 * DI];
__device__ float g_xconv [ML * DI];
__device__ float g_xdbl  [ML * XD];
__device__ float g_delta [ML * DI];
__device__ float g_S     [ML * DI];
__device__ float g_ylocal[ML * DI];
__device__ float g_hend  [BSZ * NCH * DS * DI];
__device__ float g_hin   [BSZ * NCH * DS * DI];
__device__ float g_Aneg  [DI * DS];

// split-bf16 operand buffers (ushort bit patterns)
__device__ unsigned short g_a1[ML * 3 * DM];        // hidden split   [4096 x 3072]
__device__ unsigned short g_b1[(2*DI) * 3 * DM];    // in_proj_w split[4096 x 3072]
__device__ unsigned short g_a2[ML * 3 * DI];        // yfinal split   [4096 x 6144]
__device__ unsigned short g_b2[DM * 3 * DI];        // out_proj_w split[1024 x 6144]

__device__ __forceinline__ float4 ld4(const float* p) {
    return *reinterpret_cast<const float4*>(p);
}
__device__ __forceinline__ float siluf(float x) {
    return x / (1.0f + __expf(-x));
}
__device__ __forceinline__ void split1(float x, unsigned short& hb, unsigned short& lb) {
    __nv_bfloat16 hi = __float2bfloat16(x);
    float lof = x - __bfloat162float(hi);
    __nv_bfloat16 lo = __float2bfloat16(lof);
    hb = __bfloat16_as_ushort(hi);
    lb = __bfloat16_as_ushort(lo);
}

// ---------------- split-bf16 conversion (vectorized, 4 elems/thread) ------------
// mode 0 (A operand): Y[M,3K] = [hi | hi | lo]
// mode 1 (B operand): Y[M,3K] = [hi | lo | hi]
// Together: A'.B' = hi.hi + hi.lo + lo.hi  (lo.lo dropped, ~2^-18 relative)
__global__ __launch_bounds__(256) void split_bf16_kernel(
    const float* __restrict__ X, unsigned short* __restrict__ Y,
    int K, int total4, int mode)
{
    int idx4 = blockIdx.x * 256 + threadIdx.x;
    if (idx4 >= total4) return;
    int idx = idx4 * 4;                 // K is a multiple of 4
    int m = idx / K;
    int k = idx - m * K;
    float4 v = ld4(X + idx);
    unsigned short hb[4], lb[4];
    split1(v.x, hb[0], lb[0]); split1(v.y, hb[1], lb[1]);
    split1(v.z, hb[2], lb[2]); split1(v.w, hb[3], lb[3]);
    size_t base = (size_t)m * 3 * K + k;
    ushort4 H = make_ushort4(hb[0], hb[1], hb[2], hb[3]);
    ushort4 L = make_ushort4(lb[0], lb[1], lb[2], lb[3]);
    *reinterpret_cast<ushort4*>(Y + base) = H;
    if (mode == 0) {
        *reinterpret_cast<ushort4*>(Y + base + K)     = H;
        *reinterpret_cast<ushort4*>(Y + base + 2 * K) = L;
    } else {
        *reinterpret_cast<ushort4*>(Y + base + K)     = L;
        *reinterpret_cast<ushort4*>(Y + base + 2 * K) = H;
    }
}

// ---------------- bf16 tensor-core GEMM: C = A[M,K2] * B[N,K2]^T ----------------
// 128x128 block tile, 128 threads, 4 warps of 64x64, double-buffered cp.async.
// TBK=64: one sync pair per 64-k chunk (halved barrier count vs TBK=32).
#define TBK 64
#define SPAD 8
#define SLD  (TBK + SPAD)                 // 72 ushorts per smem row
#define STAGE_USH (2 * 128 * SLD)         // A tile + B tile, one stage
#define GEMM_SMEM_BYTES (2 * STAGE_USH * 2)   // 2 stages * ushort

__device__ __forceinline__ void cpasync16(unsigned int saddr, const void* gptr) {
    asm volatile("cp.async.cg.shared.global [%0], [%1], 16;\n" :: "r"(saddr), "l"(gptr));
}

__global__ __launch_bounds__(128) void gemm_bf16_split(
    const unsigned short* __restrict__ A,   // [M][K2] bf16 bits
    const unsigned short* __restrict__ B,   // [N][K2] bf16 bits
    float* __restrict__ C, int ldc,
    int K2)
{
    extern __shared__ __align__(16) unsigned short smem_u[];

    const int tid  = threadIdx.x;
    const int lane = tid & 31;
    const int wid  = tid >> 5;
    const int wm   = (wid >> 1) * 64;    // warp M offset
    const int wn   = (wid & 1) * 64;     // warp N offset
    const int row0 = blockIdx.y * 128;
    const int col0 = blockIdx.x * 128;

    const int T = K2 / TBK;

    float acc[4][8][4];
#pragma unroll
    for (int mi = 0; mi < 4; mi++)
#pragma unroll
        for (int ni = 0; ni < 8; ni++)
#pragma unroll
            for (int q = 0; q < 4; q++) acc[mi][ni][q] = 0.0f;

    auto issue = [&](int t, int buf) {
        int kk = t * TBK;
        unsigned short* sa = smem_u + buf * STAGE_USH;
        unsigned short* sb = sa + 128 * SLD;
#pragma unroll
        for (int i = 0; i < 8; i++) {
            int e = tid + 128 * i;
            int r = e >> 3;
            int c = e & 7;
            unsigned int pa = (unsigned int)__cvta_generic_to_shared(&sa[r * SLD + c * 8]);
            cpasync16(pa, A + (size_t)(row0 + r) * K2 + kk + c * 8);
            unsigned int pb = (unsigned int)__cvta_generic_to_shared(&sb[r * SLD + c * 8]);
            cpasync16(pb, B + (size_t)(col0 + r) * K2 + kk + c * 8);
        }
        asm volatile("cp.async.commit_group;\n");
    };

    issue(0, 0);

    for (int t = 0; t < T; t++) {
        if (t + 1 < T) {
            issue(t + 1, (t + 1) & 1);
            asm volatile("cp.async.wait_group 1;\n");
        } else {
            asm volatile("cp.async.wait_group 0;\n");
        }
        __syncthreads();

        const unsigned short* As = smem_u + (t & 1) * STAGE_USH;
        const unsigned short* Bs = As + 128 * SLD;

#pragma unroll
        for (int ks = 0; ks < 4; ks++) {
            const int kc = ks * 16 + (lane & 3) * 2;
            unsigned int af[4][4], bf[8][2];
#pragma unroll
            for (int mi = 0; mi < 4; mi++) {
                int r = wm + mi * 16 + (lane >> 2);
                af[mi][0] = *(const unsigned int*)&As[r * SLD + kc];
                af[mi][1] = *(const unsigned int*)&As[(r + 8) * SLD + kc];
                af[mi][2] = *(const unsigned int*)&As[r * SLD + kc + 8];
                af[mi][3] = *(const unsigned int*)&As[(r + 8) * SLD + kc + 8];
            }
#pragma unroll
            for (int ni = 0; ni < 8; ni++) {
                int n = wn + ni * 8 + (lane >> 2);
                bf[ni][0] = *(const unsigned int*)&Bs[n * SLD + kc];
                bf[ni][1] = *(const unsigned int*)&Bs[n * SLD + kc + 8];
            }
#pragma unroll
            for (int mi = 0; mi < 4; mi++)
#pragma unroll
                for (int ni = 0; ni < 8; ni++) {
                    asm volatile(
                        "mma.sync.aligned.m16n8k16.row.col.f32.bf16.bf16.f32 "
                        "{%0,%1,%2,%3}, {%4,%5,%6,%7}, {%8,%9}, {%0,%1,%2,%3};"
                        : "+f"(acc[mi][ni][0]), "+f"(acc[mi][ni][1]),
                          "+f"(acc[mi][ni][2]), "+f"(acc[mi][ni][3])
                        : "r"(af[mi][0]), "r"(af[mi][1]), "r"(af[mi][2]), "r"(af[mi][3]),
                          "r"(bf[ni][0]), "r"(bf[ni][1]));
                }
        }
        __syncthreads();
    }

    // epilogue
#pragma unroll
    for (int mi = 0; mi < 4; mi++) {
        int r = row0 + wm + mi * 16 + (lane >> 2);
#pragma unroll
        for (int ni = 0; ni < 8; ni++) {
            int cn = col0 + wn + ni * 8 + (lane & 3) * 2;
            *(float2*)&C[(size_t)r * ldc + cn] =
                make_float2(acc[mi][ni][0], acc[mi][ni][1]);
            *(float2*)&C[(size_t)(r + 8) * ldc + cn] =
                make_float2(acc[mi][ni][2], acc[mi][ni][3]);
        }
    }
}

// ---------------- fp32 tiled SGEMM (kept for dt_proj, K=64) ---------------------
#define BM 128
#define BN 128
#define BKK 16

__global__ __launch_bounds__(256) void sgemm_tn(
    const float* __restrict__ A, int lda,
    const float* __restrict__ B, int ldb,
    float* __restrict__ C, int ldc,
    int M, int N, int K,
    const float* __restrict__ bias, int epi)
{
    __shared__ __align__(16) float As[BKK][BM + 4];
    __shared__ __align__(16) float Bs[BKK][BN + 4];

    const int tid = threadIdx.x;
    const int tx = tid & 15;
    const int ty = tid >> 4;
    const int row0 = blockIdx.y * BM;
    const int col0 = blockIdx.x * BN;

    const int lm = tid >> 1;
    const int lk = (tid & 1) * 8;

    float acc[8][8];
#pragma unroll
    for (int i = 0; i < 8; i++)
#pragma unroll
        for (int j = 0; j < 8; j++) acc[i][j] = 0.0f;

    for (int kk = 0; kk < K; kk += BKK) {
        {
            int gr = row0 + lm;
            float4 v0 = make_float4(0.f,0.f,0.f,0.f), v1 = v0;
            if (gr < M) {
                const float* p = A + (size_t)gr * lda + kk + lk;
                v0 = ld4(p); v1 = ld4(p + 4);
            }
            As[lk+0][lm] = v0.x; As[lk+1][lm] = v0.y;
            As[lk+2][lm] = v0.z; As[lk+3][lm] = v0.w;
            As[lk+4][lm] = v1.x; As[lk+5][lm] = v1.y;
            As[lk+6][lm] = v1.z; As[lk+7][lm] = v1.w;
        }
        {
            int gn = col0 + lm;
            float4 v0 = make_float4(0.f,0.f,0.f,0.f), v1 = v0;
            if (gn < N) {
                const float* p = B + (size_t)gn * ldb + kk + lk;
                v0 = ld4(p); v1 = ld4(p + 4);
            }
            Bs[lk+0][lm] = v0.x; Bs[lk+1][lm] = v0.y;
            Bs[lk+2][lm] = v0.z; Bs[lk+3][lm] = v0.w;
            Bs[lk+4][lm] = v1.x; Bs[lk+5][lm] = v1.y;
            Bs[lk+6][lm] = v1.z; Bs[lk+7][lm] = v1.w;
        }
        __syncthreads();

#pragma unroll
        for (int k = 0; k < BKK; k++) {
            float4 a0 = *reinterpret_cast<const float4*>(&As[k][ty*8]);
            float4 a1 = *reinterpret_cast<const float4*>(&As[k][ty*8+4]);
            float4 b0 = *reinterpret_cast<const float4*>(&Bs[k][tx*8]);
            float4 b1 = *reinterpret_cast<const float4*>(&Bs[k][tx*8+4]);
            float av[8] = {a0.x,a0.y,a0.z,a0.w,a1.x,a1.y,a1.z,a1.w};
            float bv[8] = {b0.x,b0.y,b0.z,b0.w,b1.x,b1.y,b1.z,b1.w};
#pragma unroll
            for (int i = 0; i < 8; i++)
#pragma unroll
                for (int j = 0; j < 8; j++)
                    acc[i][j] = fmaf(av[i], bv[j], acc[i][j]);
        }
        __syncthreads();
    }

#pragma unroll
    for (int i = 0; i < 8; i++) {
        int r = row0 + ty*8 + i;
        if (r >= M) continue;
#pragma unroll
        for (int j = 0; j < 8; j++) {
            int c = col0 + tx*8 + j;
            if (c >= N) continue;
            float v = acc[i][j];
            if (epi == 1) {
                v += bias[c];
                v = (v > 20.0f) ? v : log1pf(__expf(v));   // softplus
            }
            C[(size_t)r * ldc + c] = v;
        }
    }
}

// ---------------- depthwise causal conv (K=4) + bias + SiLU ---------------------
__global__ __launch_bounds__(256) void conv_silu_kernel(
    const float* __restrict__ conv_w,
    const float* __restrict__ conv_b)
{
    int d = blockIdx.x * 256 + threadIdx.x;
    int l = blockIdx.y;
    int b = blockIdx.z;
    float4 w = ld4(conv_w + d * 4);
    const float wv[4] = {w.x, w.y, w.z, w.w};
    float acc = conv_b[d];
    int base = b * SEQL;
#pragma unroll
    for (int k = 0; k < 4; k++) {
        int li = l - 3 + k;
        if (li >= 0)
            acc = fmaf(g_xz[(size_t)(base + li) * (2*DI) + d], wv[k], acc);
    }
    g_xconv[(size_t)(base + l) * DI + d] = siluf(acc);
}

// ---------------- x_proj GEMM: split-K x8 with atomic accumulation --------------
__global__ __launch_bounds__(256) void gemm_xdbl_splitk(
    const float* __restrict__ W)   // x_proj_w [96, 2048]
{
    __shared__ float As[32][33];
    __shared__ float Ws[96][33];
    int tid = threadIdx.x;
    int row0 = blockIdx.x * 32;
    int kq = blockIdx.y;           // 0..7, K chunk of 256
    int r = tid & 31;
    int g = tid >> 5;
    float acc[12];
#pragma unroll
    for (int j = 0; j < 12; j++) acc[j] = 0.0f;

    for (int kk = kq * 256; kk < (kq + 1) * 256; kk += 32) {
#pragma unroll
        for (int i = 0; i < 4; i++) {
            int e = tid + i * 256;
            int m = e >> 5, k = e & 31;
            As[m][k] = g_xconv[(size_t)(row0 + m) * DI + kk + k];
        }
#pragma unroll
        for (int i = 0; i < 12; i++) {
            int e = tid + i * 256;
            int n = e >> 5, k = e & 31;
            Ws[n][k] = W[(size_t)n * DI + kk + k];
        }
        __syncthreads();
#pragma unroll
        for (int k = 0; k < 32; k++) {
            float a = As[r][k];
#pragma unroll
            for (int j = 0; j < 12; j++)
                acc[j] = fmaf(a, Ws[g*12 + j][k], acc[j]);
        }
        __syncthreads();
    }
#pragma unroll
    for (int j = 0; j < 12; j++)
        atomicAdd(&g_xdbl[(size_t)(row0 + r) * XD + g*12 + j], acc[j]);
}

// ---------------- prep: Aneg = -exp(A_log) --------------------------------------
__global__ void prep_A_kernel(const float* __restrict__ A_log) {
    int i = blockIdx.x * 256 + threadIdx.x;
    if (i < DI * DS) g_Aneg[i] = -__expf(A_log[i]);
}

// ---------------- scan phase A: chunk-local scan (h0 = 0) -----------------------
__global__ __launch_bounds__(256) void scanA_kernel()
{
    int bc = blockIdx.x;
    int d     = (bc & 7) * 256 + threadIdx.x;
    int chunk = (bc >> 3) & 15;
    int b     = bc >> 7;

    float a[DS], h[DS];
#pragma unroll
    for (int n = 0; n < DS; n++) { a[n] = g_Aneg[d * DS + n]; h[n] = 0.0f; }
    float S = 0.0f;
    int l0 = chunk * CT;

    for (int t = 0; t < CT; t++) {
        size_t base = (size_t)(b * SEQL + l0 + t);
        float dlt = g_delta[base * DI + d];
        float u   = g_xconv[base * DI + d];
        S += dlt;
        g_S[base * DI + d] = S;
        float du = dlt * u;
        const float* bc_ptr = g_xdbl + base * XD + RNK;
        float4 B0 = ld4(bc_ptr), B1 = ld4(bc_ptr + 4);
        float4 B2 = ld4(bc_ptr + 8), B3 = ld4(bc_ptr + 12);
        float4 C0 = ld4(bc_ptr + 16), C1 = ld4(bc_ptr + 20);
        float4 C2 = ld4(bc_ptr + 24), C3 = ld4(bc_ptr + 28);
        float Bv[DS] = {B0.x,B0.y,B0.z,B0.w,B1.x,B1.y,B1.z,B1.w,
                        B2.x,B2.y,B2.z,B2.w,B3.x,B3.y,B3.z,B3.w};
        float Cv[DS] = {C0.x,C0.y,C0.z,C0.w,C1.x,C1.y,C1.z,C1.w,
                        C2.x,C2.y,C2.z,C2.w,C3.x,C3.y,C3.z,C3.w};
        float y = 0.0f;
#pragma unroll
        for (int n = 0; n < DS; n++) {
            float dA = __expf(a[n] * dlt);
            h[n] = fmaf(h[n], dA, du * Bv[n]);
            y = fmaf(h[n], Cv[n], y);
        }
        g_ylocal[base * DI + d] = y;
    }
#pragma unroll
    for (int n = 0; n < DS; n++)
        g_hend[((size_t)(b * NCH + chunk) * DS + n) * DI + d] = h[n];
}

// ---------------- scan phase B: cross-chunk prefix (16 steps) -------------------
__global__ __launch_bounds__(256) void scanB_kernel()
{
    int bc = blockIdx.x;
    int d = (bc & 7) * 256 + threadIdx.x;
    int n = (bc >> 3) & 15;
    int b = bc >> 7;
    float an = g_Aneg[d * DS + n];
    float hin = 0.0f;
    for (int c = 0; c < NCH; c++) {
        size_t idx = ((size_t)(b * NCH + c) * DS + n) * DI + d;
        g_hin[idx] = hin;
        float Sc = g_S[(size_t)(b * SEQL + c * CT + CT - 1) * DI + d];
        hin = fmaf(hin, __expf(an * Sc), g_hend[idx]);
    }
}

// ---------------- scan phase C: correction + D*x + silu(z) gate + bf16 split ----
// Writes the GEMM2 A-operand (g_a2, mode-0 split [hi|hi|lo]) directly.
__global__ __launch_bounds__(256) void scanC_kernel(const float* __restrict__ Dp)
{
    int d = blockIdx.x * 256 + threadIdx.x;
    int l = blockIdx.y;
    int b = blockIdx.z;
    size_t base = (size_t)(b * SEQL + l);
    int chunk = l >> 7;

    float S = g_S[base * DI + d];
    float y = g_ylocal[base * DI + d];
    const float* cp = g_xdbl + base * XD + RNK + DS;
    float4 C0 = ld4(cp), C1 = ld4(cp + 4), C2 = ld4(cp + 8), C3 = ld4(cp + 12);
    float Cv[DS] = {C0.x,C0.y,C0.z,C0.w,C1.x,C1.y,C1.z,C1.w,
                    C2.x,C2.y,C2.z,C2.w,C3.x,C3.y,C3.z,C3.w};
#pragma unroll
    for (int n = 0; n < DS; n++) {
        float an = g_Aneg[d * DS + n];
        float hin = g_hin[((size_t)(b * NCH + chunk) * DS + n) * DI + d];
        y = fmaf(Cv[n] * __expf(an * S), hin, y);
    }
    float x = g_xconv[base * DI + d];
    float z = g_xz[base * (2*DI) + DI + d];
    y = fmaf(Dp[d], x, y);
    y = y * siluf(z);

    // fused mode-0 split-bf16 write of the GEMM2 A operand
    unsigned short hb, lb;
    split1(y, hb, lb);
    size_t ob = base * (3 * DI) + d;
    g_a2[ob]          = hb;
    g_a2[ob + DI]     = hb;
    g_a2[ob + 2 * DI] = lb;
}

// ---------------- launch --------------------------------------------------------
extern "C" void kernel_launch(void* const* d_in, const int* in_sizes, int n_in,
                              void* d_out, int out_size)
{
    const float* hidden    = (const float*)d_in[0];   // [2,2048,1024]
    const float* in_proj_w = (const float*)d_in[1];   // [4096,1024]
    const float* conv_w    = (const float*)d_in[2];   // [2048,1,4]
    const float* conv_b    = (const float*)d_in[3];   // [2048]
    const float* x_proj_w  = (const float*)d_in[4];   // [96,2048]
    const float* dt_proj_w = (const float*)d_in[5];   // [2048,64]
    const float* dt_proj_b = (const float*)d_in[6];   // [2048]
    const float* A_log     = (const float*)d_in[7];   // [2048,16]
    const float* Dp        = (const float*)d_in[8];   // [2048]
    const float* out_proj_w= (const float*)d_in[9];   // [1024,2048]
    float* out = (float*)d_out;                       // [2,2048,1024]

    float* xz     = nullptr; cudaGetSymbolAddress((void**)&xz,     g_xz);
    float* xdbl   = nullptr; cudaGetSymbolAddress((void**)&xdbl,   g_xdbl);
    float* delta  = nullptr; cudaGetSymbolAddress((void**)&delta,  g_delta);
    unsigned short* a1 = nullptr; cudaGetSymbolAddress((void**)&a1, g_a1);
    unsigned short* b1 = nullptr; cudaGetSymbolAddress((void**)&b1, g_b1);
    unsigned short* a2 = nullptr; cudaGetSymbolAddress((void**)&a2, g_a2);
    unsigned short* b2 = nullptr; cudaGetSymbolAddress((void**)&b2, g_b2);

    cudaFuncSetAttribute(gemm_bf16_split,
                         cudaFuncAttributeMaxDynamicSharedMemorySize, GEMM_SMEM_BYTES);

    // 0) split-bf16 conversions for GEMM1 (A: [hi|hi|lo], B: [hi|lo|hi])
    {
        int tot4 = (ML * DM) / 4;
        split_bf16_kernel<<<(tot4 + 255)/256, 256>>>(hidden, a1, DM, tot4, 0);
        tot4 = ((2*DI) * DM) / 4;
        split_bf16_kernel<<<(tot4 + 255)/256, 256>>>(in_proj_w, b1, DM, tot4, 1);
    }
    // 1) xz = hidden @ in_proj_w^T  (HMMA split-bf16, K2 = 3*1024)
    gemm_bf16_split<<<dim3((2*DI)/128, ML/128), 128, GEMM_SMEM_BYTES>>>(
        a1, b1, xz, 2*DI, 3*DM);
    // 2) depthwise conv + silu
    conv_silu_kernel<<<dim3(DI/256, SEQL, BSZ), 256>>>(conv_w, conv_b);
    // 3) Aneg = -exp(A_log)
    prep_A_kernel<<<(DI*DS + 255)/256, 256>>>(A_log);
    // 4) x_dbl = xconv @ x_proj_w^T  (split-K x8 + atomics)
    cudaMemsetAsync(xdbl, 0, (size_t)ML * XD * sizeof(float));
    gemm_xdbl_splitk<<<dim3(ML/32, 8), 256>>>(x_proj_w);
    // 5) delta = softplus(x_dbl[:, :64] @ dt_proj_w^T + b)
    sgemm_tn<<<dim3(DI/BN, ML/BM), 256>>>(xdbl, XD, dt_proj_w, RNK,
                                          delta, DI, ML, DI, RNK, dt_proj_b, 1);
    // 6) chunked selective scan (scanC fuses the GEMM2 A-operand split)
    scanA_kernel<<<BSZ*NCH*(DI/256), 256>>>();
    scanB_kernel<<<BSZ*DS*(DI/256), 256>>>();
    scanC_kernel<<<dim3(DI/256, SEQL, BSZ), 256>>>(Dp);
    // 7) split-bf16 conversion for GEMM2 B operand
    {
        int tot4 = (DM * DI) / 4;
        split_bf16_kernel<<<(tot4 + 255)/256, 256>>>(out_proj_w, b2, DI, tot4, 1);
    }
    // 8) out = yfinal @ out_proj_w^T  (HMMA split-bf16, K2 = 3*2048)
    gemm_bf16_split<<<dim3(DM/128, ML/128), 128, GEMM_SMEM_BYTES>>>(
        a2, b2, out, DM, 3*DI);
}

// round 12
// speedup vs baseline: 1.9194x; 1.0589x over previous
#include <cuda_runtime.h>
#include <cuda_bf16.h>
#include <stdint.h>
#include <math.h>

// Problem constants (fixed by the dataset)
#define BSZ   2
#define SEQL  2048
#define DM    1024
#define DI    2048      // d_inner
#define DS    16        // d_state
#define RNK   64        // dt_rank
#define XD    96        // dt_rank + 2*d_state
#define NCH   16        // number of scan chunks
#define CT    128       // chunk length (NCH*CT == SEQL)
#define ML    (BSZ*SEQL)  // 4096 rows

// ---------------- scratch (static __device__, no runtime alloc) ----------------
__device__ float g_xz    [ML * 2 * DI];
__device__ float g_xconv [ML * DI];
__device__ float g_xdbl  [ML * XD];
__device__ float g_delta [ML * DI];
__device__ float g_S     [ML * DI];
__device__ float g_ylocal[ML * DI];
__device__ float g_hend  [BSZ * NCH * DS * DI];
__device__ float g_hin   [BSZ * NCH * DS * DI];
__device__ float g_Aneg  [DI * DS];

// split-bf16 operand buffers (ushort bit patterns)
__device__ unsigned short g_a1[ML * 3 * DM];        // hidden split   [4096 x 3072]
__device__ unsigned short g_b1[(2*DI) * 3 * DM];    // in_proj_w split[4096 x 3072]
__device__ unsigned short g_a2[ML * 3 * DI];        // yfinal split   [4096 x 6144]
__device__ unsigned short g_b2[DM * 3 * DI];        // out_proj_w split[1024 x 6144]

__device__ __forceinline__ float4 ld4(const float* p) {
    return *reinterpret_cast<const float4*>(p);
}
__device__ __forceinline__ float siluf(float x) {
    return x / (1.0f + __expf(-x));
}
__device__ __forceinline__ void split1(float x, unsigned short& hb, unsigned short& lb) {
    __nv_bfloat16 hi = __float2bfloat16(x);
    float lof = x - __bfloat162float(hi);
    __nv_bfloat16 lo = __float2bfloat16(lof);
    hb = __bfloat16_as_ushort(hi);
    lb = __bfloat16_as_ushort(lo);
}

// ---------------- split-bf16 conversion (vectorized, 4 elems/thread) ------------
// mode 0 (A operand): Y[M,3K] = [hi | hi | lo]
// mode 1 (B operand): Y[M,3K] = [hi | lo | hi]
// Together: A'.B' = hi.hi + hi.lo + lo.hi  (lo.lo dropped, ~2^-18 relative)
__global__ __launch_bounds__(256) void split_bf16_kernel(
    const float* __restrict__ X, unsigned short* __restrict__ Y,
    int K, int total4, int mode)
{
    int idx4 = blockIdx.x * 256 + threadIdx.x;
    if (idx4 >= total4) return;
    int idx = idx4 * 4;                 // K is a multiple of 4
    int m = idx / K;
    int k = idx - m * K;
    float4 v = ld4(X + idx);
    unsigned short hb[4], lb[4];
    split1(v.x, hb[0], lb[0]); split1(v.y, hb[1], lb[1]);
    split1(v.z, hb[2], lb[2]); split1(v.w, hb[3], lb[3]);
    size_t base = (size_t)m * 3 * K + k;
    ushort4 H = make_ushort4(hb[0], hb[1], hb[2], hb[3]);
    ushort4 L = make_ushort4(lb[0], lb[1], lb[2], lb[3]);
    *reinterpret_cast<ushort4*>(Y + base) = H;
    if (mode == 0) {
        *reinterpret_cast<ushort4*>(Y + base + K)     = H;
        *reinterpret_cast<ushort4*>(Y + base + 2 * K) = L;
    } else {
        *reinterpret_cast<ushort4*>(Y + base + K)     = L;
        *reinterpret_cast<ushort4*>(Y + base + 2 * K) = H;
    }
}

// ---------------- bf16 tensor-core GEMM: C = A[M,K2] * B[N,K2]^T ----------------
// 128x128 block tile, 128 threads, 4 warps of 64x64, double-buffered cp.async.
// TBK=64; fragment loads via ldmatrix.m8n8.x4 (4x fewer shared-load issues).
#define TBK 64
#define SPAD 8
#define SLD  (TBK + SPAD)                 // 72 ushorts per smem row
#define STAGE_USH (2 * 128 * SLD)         // A tile + B tile, one stage
#define GEMM_SMEM_BYTES (2 * STAGE_USH * 2)   // 2 stages * ushort

__device__ __forceinline__ void cpasync16(unsigned int saddr, const void* gptr) {
    asm volatile("cp.async.cg.shared.global [%0], [%1], 16;\n" :: "r"(saddr), "l"(gptr));
}
__device__ __forceinline__ void ldsm_x4(unsigned int addr,
    unsigned int& r0, unsigned int& r1, unsigned int& r2, unsigned int& r3)
{
    asm volatile("ldmatrix.sync.aligned.m8n8.x4.shared.b16 {%0,%1,%2,%3}, [%4];"
        : "=r"(r0), "=r"(r1), "=r"(r2), "=r"(r3) : "r"(addr));
}

__global__ __launch_bounds__(128) void gemm_bf16_split(
    const unsigned short* __restrict__ A,   // [M][K2] bf16 bits
    const unsigned short* __restrict__ B,   // [N][K2] bf16 bits
    float* __restrict__ C, int ldc,
    int K2)
{
    extern __shared__ __align__(16) unsigned short smem_u[];

    const int tid  = threadIdx.x;
    const int lane = tid & 31;
    const int wid  = tid >> 5;
    const int wm   = (wid >> 1) * 64;    // warp M offset
    const int wn   = (wid & 1) * 64;     // warp N offset
    const int row0 = blockIdx.y * 128;
    const int col0 = blockIdx.x * 128;

    const int T = K2 / TBK;

    // ldmatrix per-lane address components (element offsets within a tile)
    // A (x4 covering m16 x k16 for one mi):
    //   lanes 0-7: m0-7@k0 | 8-15: m8-15@k0 | 16-23: m0-7@k8 | 24-31: m8-15@k8
    const int aRow = wm + (lane & 15);
    const int aK   = (lane >> 4) << 3;
    // B (x4 covering two n8 x k16 fragments: ni and ni+1):
    //   lanes 0-7: n0-7@k0 | 8-15: n0-7@k8 | 16-23: n8-15@k0 | 24-31: n8-15@k8
    const int bRow = wn + (lane & 7) + ((lane >> 4) << 3);
    const int bK   = ((lane >> 3) & 1) << 3;

    float acc[4][8][4];
#pragma unroll
    for (int mi = 0; mi < 4; mi++)
#pragma unroll
        for (int ni = 0; ni < 8; ni++)
#pragma unroll
            for (int q = 0; q < 4; q++) acc[mi][ni][q] = 0.0f;

    auto issue = [&](int t, int buf) {
        int kk = t * TBK;
        unsigned short* sa = smem_u + buf * STAGE_USH;
        unsigned short* sb = sa + 128 * SLD;
#pragma unroll
        for (int i = 0; i < 8; i++) {
            int e = tid + 128 * i;
            int r = e >> 3;
            int c = e & 7;
            unsigned int pa = (unsigned int)__cvta_generic_to_shared(&sa[r * SLD + c * 8]);
            cpasync16(pa, A + (size_t)(row0 + r) * K2 + kk + c * 8);
            unsigned int pb = (unsigned int)__cvta_generic_to_shared(&sb[r * SLD + c * 8]);
            cpasync16(pb, B + (size_t)(col0 + r) * K2 + kk + c * 8);
        }
        asm volatile("cp.async.commit_group;\n");
    };

    issue(0, 0);

    for (int t = 0; t < T; t++) {
        if (t + 1 < T) {
            issue(t + 1, (t + 1) & 1);
            asm volatile("cp.async.wait_group 1;\n");
        } else {
            asm volatile("cp.async.wait_group 0;\n");
        }
        __syncthreads();

        const unsigned short* As = smem_u + (t & 1) * STAGE_USH;
        const unsigned short* Bs = As + 128 * SLD;
        unsigned int aAddr = (unsigned int)__cvta_generic_to_shared(
            &As[aRow * SLD + aK]);
        unsigned int bAddr = (unsigned int)__cvta_generic_to_shared(
            &Bs[bRow * SLD + bK]);

#pragma unroll
        for (int ks = 0; ks < 4; ks++) {
            const unsigned int kOff = (ks * 16) * 2;   // bytes
            unsigned int af[4][4], bf[8][2];
#pragma unroll
            for (int mi = 0; mi < 4; mi++) {
                ldsm_x4(aAddr + kOff + (unsigned)(mi * 16 * SLD) * 2,
                        af[mi][0], af[mi][1], af[mi][2], af[mi][3]);
            }
#pragma unroll
            for (int nj = 0; nj < 4; nj++) {
                ldsm_x4(bAddr + kOff + (unsigned)(nj * 16 * SLD) * 2,
                        bf[2*nj][0], bf[2*nj][1], bf[2*nj+1][0], bf[2*nj+1][1]);
            }
#pragma unroll
            for (int mi = 0; mi < 4; mi++)
#pragma unroll
                for (int ni = 0; ni < 8; ni++) {
                    asm volatile(
                        "mma.sync.aligned.m16n8k16.row.col.f32.bf16.bf16.f32 "
                        "{%0,%1,%2,%3}, {%4,%5,%6,%7}, {%8,%9}, {%0,%1,%2,%3};"
                        : "+f"(acc[mi][ni][0]), "+f"(acc[mi][ni][1]),
                          "+f"(acc[mi][ni][2]), "+f"(acc[mi][ni][3])
                        : "r"(af[mi][0]), "r"(af[mi][1]), "r"(af[mi][2]), "r"(af[mi][3]),
                          "r"(bf[ni][0]), "r"(bf[ni][1]));
                }
        }
        __syncthreads();
    }

    // epilogue
#pragma unroll
    for (int mi = 0; mi < 4; mi++) {
        int r = row0 + wm + mi * 16 + (lane >> 2);
#pragma unroll
        for (int ni = 0; ni < 8; ni++) {
            int cn = col0 + wn + ni * 8 + (lane & 3) * 2;
            *(float2*)&C[(size_t)r * ldc + cn] =
                make_float2(acc[mi][ni][0], acc[mi][ni][1]);
            *(float2*)&C[(size_t)(r + 8) * ldc + cn] =
                make_float2(acc[mi][ni][2], acc[mi][ni][3]);
        }
    }
}

// ---------------- fp32 tiled SGEMM (kept for dt_proj, K=64) ---------------------
#define BM 128
#define BN 128
#define BKK 16

__global__ __launch_bounds__(256) void sgemm_tn(
    const float* __restrict__ A, int lda,
    const float* __restrict__ B, int ldb,
    float* __restrict__ C, int ldc,
    int M, int N, int K,
    const float* __restrict__ bias, int epi)
{
    __shared__ __align__(16) float As[BKK][BM + 4];
    __shared__ __align__(16) float Bs[BKK][BN + 4];

    const int tid = threadIdx.x;
    const int tx = tid & 15;
    const int ty = tid >> 4;
    const int row0 = blockIdx.y * BM;
    const int col0 = blockIdx.x * BN;

    const int lm = tid >> 1;
    const int lk = (tid & 1) * 8;

    float acc[8][8];
#pragma unroll
    for (int i = 0; i < 8; i++)
#pragma unroll
        for (int j = 0; j < 8; j++) acc[i][j] = 0.0f;

    for (int kk = 0; kk < K; kk += BKK) {
        {
            int gr = row0 + lm;
            float4 v0 = make_float4(0.f,0.f,0.f,0.f), v1 = v0;
            if (gr < M) {
                const float* p = A + (size_t)gr * lda + kk + lk;
                v0 = ld4(p); v1 = ld4(p + 4);
            }
            As[lk+0][lm] = v0.x; As[lk+1][lm] = v0.y;
            As[lk+2][lm] = v0.z; As[lk+3][lm] = v0.w;
            As[lk+4][lm] = v1.x; As[lk+5][lm] = v1.y;
            As[lk+6][lm] = v1.z; As[lk+7][lm] = v1.w;
        }
        {
            int gn = col0 + lm;
            float4 v0 = make_float4(0.f,0.f,0.f,0.f), v1 = v0;
            if (gn < N) {
                const float* p = B + (size_t)gn * ldb + kk + lk;
                v0 = ld4(p); v1 = ld4(p + 4);
            }
            Bs[lk+0][lm] = v0.x; Bs[lk+1][lm] = v0.y;
            Bs[lk+2][lm] = v0.z; Bs[lk+3][lm] = v0.w;
            Bs[lk+4][lm] = v1.x; Bs[lk+5][lm] = v1.y;
            Bs[lk+6][lm] = v1.z; Bs[lk+7][lm] = v1.w;
        }
        __syncthreads();

#pragma unroll
        for (int k = 0; k < BKK; k++) {
            float4 a0 = *reinterpret_cast<const float4*>(&As[k][ty*8]);
            float4 a1 = *reinterpret_cast<const float4*>(&As[k][ty*8+4]);
            float4 b0 = *reinterpret_cast<const float4*>(&Bs[k][tx*8]);
            float4 b1 = *reinterpret_cast<const float4*>(&Bs[k][tx*8+4]);
            float av[8] = {a0.x,a0.y,a0.z,a0.w,a1.x,a1.y,a1.z,a1.w};
            float bv[8] = {b0.x,b0.y,b0.z,b0.w,b1.x,b1.y,b1.z,b1.w};
#pragma unroll
            for (int i = 0; i < 8; i++)
#pragma unroll
                for (int j = 0; j < 8; j++)
                    acc[i][j] = fmaf(av[i], bv[j], acc[i][j]);
        }
        __syncthreads();
    }

#pragma unroll
    for (int i = 0; i < 8; i++) {
        int r = row0 + ty*8 + i;
        if (r >= M) continue;
#pragma unroll
        for (int j = 0; j < 8; j++) {
            int c = col0 + tx*8 + j;
            if (c >= N) continue;
            float v = acc[i][j];
            if (epi == 1) {
                v += bias[c];
                v = (v > 20.0f) ? v : log1pf(__expf(v));   // softplus
            }
            C[(size_t)r * ldc + c] = v;
        }
    }
}

// ---------------- depthwise causal conv (K=4) + bias + SiLU ---------------------
__global__ __launch_bounds__(256) void conv_silu_kernel(
    const float* __restrict__ conv_w,
    const float* __restrict__ conv_b)
{
    int d = blockIdx.x * 256 + threadIdx.x;
    int l = blockIdx.y;
    int b = blockIdx.z;
    float4 w = ld4(conv_w + d * 4);
    const float wv[4] = {w.x, w.y, w.z, w.w};
    float acc = conv_b[d];
    int base = b * SEQL;
#pragma unroll
    for (int k = 0; k < 4; k++) {
        int li = l - 3 + k;
        if (li >= 0)
            acc = fmaf(g_xz[(size_t)(base + li) * (2*DI) + d], wv[k], acc);
    }
    g_xconv[(size_t)(base + l) * DI + d] = siluf(acc);
}

// ---------------- x_proj GEMM: split-K x8 with atomic accumulation --------------
__global__ __launch_bounds__(256) void gemm_xdbl_splitk(
    const float* __restrict__ W)   // x_proj_w [96, 2048]
{
    __shared__ float As[32][33];
    __shared__ float Ws[96][33];
    int tid = threadIdx.x;
    int row0 = blockIdx.x * 32;
    int kq = blockIdx.y;           // 0..7, K chunk of 256
    int r = tid & 31;
    int g = tid >> 5;
    float acc[12];
#pragma unroll
    for (int j = 0; j < 12; j++) acc[j] = 0.0f;

    for (int kk = kq * 256; kk < (kq + 1) * 256; kk += 32) {
#pragma unroll
        for (int i = 0; i < 4; i++) {
            int e = tid + i * 256;
            int m = e >> 5, k = e & 31;
            As[m][k] = g_xconv[(size_t)(row0 + m) * DI + kk + k];
        }
#pragma unroll
        for (int i = 0; i < 12; i++) {
            int e = tid + i * 256;
            int n = e >> 5, k = e & 31;
            Ws[n][k] = W[(size_t)n * DI + kk + k];
        }
        __syncthreads();
#pragma unroll
        for (int k = 0; k < 32; k++) {
            float a = As[r][k];
#pragma unroll
            for (int j = 0; j < 12; j++)
                acc[j] = fmaf(a, Ws[g*12 + j][k], acc[j]);
        }
        __syncthreads();
    }
#pragma unroll
    for (int j = 0; j < 12; j++)
        atomicAdd(&g_xdbl[(size_t)(row0 + r) * XD + g*12 + j], acc[j]);
}

// ---------------- prep: Aneg = -exp(A_log) --------------------------------------
__global__ void prep_A_kernel(const float* __restrict__ A_log) {
    int i = blockIdx.x * 256 + threadIdx.x;
    if (i < DI * DS) g_Aneg[i] = -__expf(A_log[i]);
}

// ---------------- scan phase A: chunk-local scan (h0 = 0) -----------------------
__global__ __launch_bounds__(256) void scanA_kernel()
{
    int bc = blockIdx.x;
    int d     = (bc & 7) * 256 + threadIdx.x;
    int chunk = (bc >> 3) & 15;
    int b     = bc >> 7;

    float a[DS], h[DS];
#pragma unroll
    for (int n = 0; n < DS; n++) { a[n] = g_Aneg[d * DS + n]; h[n] = 0.0f; }
    float S = 0.0f;
    int l0 = chunk * CT;

    for (int t = 0; t < CT; t++) {
        size_t base = (size_t)(b * SEQL + l0 + t);
        float dlt = g_delta[base * DI + d];
        float u   = g_xconv[base * DI + d];
        S += dlt;
        g_S[base * DI + d] = S;
        float du = dlt * u;
        const float* bc_ptr = g_xdbl + base * XD + RNK;
        float4 B0 = ld4(bc_ptr), B1 = ld4(bc_ptr + 4);
        float4 B2 = ld4(bc_ptr + 8), B3 = ld4(bc_ptr + 12);
        float4 C0 = ld4(bc_ptr + 16), C1 = ld4(bc_ptr + 20);
        float4 C2 = ld4(bc_ptr + 24), C3 = ld4(bc_ptr + 28);
        float Bv[DS] = {B0.x,B0.y,B0.z,B0.w,B1.x,B1.y,B1.z,B1.w,
                        B2.x,B2.y,B2.z,B2.w,B3.x,B3.y,B3.z,B3.w};
        float Cv[DS] = {C0.x,C0.y,C0.z,C0.w,C1.x,C1.y,C1.z,C1.w,
                        C2.x,C2.y,C2.z,C2.w,C3.x,C3.y,C3.z,C3.w};
        float y = 0.0f;
#pragma unroll
        for (int n = 0; n < DS; n++) {
            float dA = __expf(a[n] * dlt);
            h[n] = fmaf(h[n], dA, du * Bv[n]);
            y = fmaf(h[n], Cv[n], y);
        }
        g_ylocal[base * DI + d] = y;
    }
#pragma unroll
    for (int n = 0; n < DS; n++)
        g_hend[((size_t)(b * NCH + chunk) * DS + n) * DI + d] = h[n];
}

// ---------------- scan phase B: cross-chunk prefix (16 steps) -------------------
__global__ __launch_bounds__(256) void scanB_kernel()
{
    int bc = blockIdx.x;
    int d = (bc & 7) * 256 + threadIdx.x;
    int n = (bc >> 3) & 15;
    int b = bc >> 7;
    float an = g_Aneg[d * DS + n];
    float hin = 0.0f;
    for (int c = 0; c < NCH; c++) {
        size_t idx = ((size_t)(b * NCH + c) * DS + n) * DI + d;
        g_hin[idx] = hin;
        float Sc = g_S[(size_t)(b * SEQL + c * CT + CT - 1) * DI + d];
        hin = fmaf(hin, __expf(an * Sc), g_hend[idx]);
    }
}

// ---------------- scan phase C: correction + D*x + silu(z) gate + bf16 split ----
// Writes the GEMM2 A-operand (g_a2, mode-0 split [hi|hi|lo]) directly.
__global__ __launch_bounds__(256) void scanC_kernel(const float* __restrict__ Dp)
{
    int d = blockIdx.x * 256 + threadIdx.x;
    int l = blockIdx.y;
    int b = blockIdx.z;
    size_t base = (size_t)(b * SEQL + l);
    int chunk = l >> 7;

    float S = g_S[base * DI + d];
    float y = g_ylocal[base * DI + d];
    const float* cp = g_xdbl + base * XD + RNK + DS;
    float4 C0 = ld4(cp), C1 = ld4(cp + 4), C2 = ld4(cp + 8), C3 = ld4(cp + 12);
    float Cv[DS] = {C0.x,C0.y,C0.z,C0.w,C1.x,C1.y,C1.z,C1.w,
                    C2.x,C2.y,C2.z,C2.w,C3.x,C3.y,C3.z,C3.w};
#pragma unroll
    for (int n = 0; n < DS; n++) {
        float an = g_Aneg[d * DS + n];
        float hin = g_hin[((size_t)(b * NCH + chunk) * DS + n) * DI + d];
        y = fmaf(Cv[n] * __expf(an * S), hin, y);
    }
    float x = g_xconv[base * DI + d];
    float z = g_xz[base * (2*DI) + DI + d];
    y = fmaf(Dp[d], x, y);
    y = y * siluf(z);

    // fused mode-0 split-bf16 write of the GEMM2 A operand
    unsigned short hb, lb;
    split1(y, hb, lb);
    size_t ob = base * (3 * DI) + d;
    g_a2[ob]          = hb;
    g_a2[ob + DI]     = hb;
    g_a2[ob + 2 * DI] = lb;
}

// ---------------- launch --------------------------------------------------------
extern "C" void kernel_launch(void* const* d_in, const int* in_sizes, int n_in,
                              void* d_out, int out_size)
{
    const float* hidden    = (const float*)d_in[0];   // [2,2048,1024]
    const float* in_proj_w = (const float*)d_in[1];   // [4096,1024]
    const float* conv_w    = (const float*)d_in[2];   // [2048,1,4]
    const float* conv_b    = (const float*)d_in[3];   // [2048]
    const float* x_proj_w  = (const float*)d_in[4];   // [96,2048]
    const float* dt_proj_w = (const float*)d_in[5];   // [2048,64]
    const float* dt_proj_b = (const float*)d_in[6];   // [2048]
    const float* A_log     = (const float*)d_in[7];   // [2048,16]
    const float* Dp        = (const float*)d_in[8];   // [2048]
    const float* out_proj_w= (const float*)d_in[9];   // [1024,2048]
    float* out = (float*)d_out;                       // [2,2048,1024]

    float* xz     = nullptr; cudaGetSymbolAddress((void**)&xz,     g_xz);
    float* xdbl   = nullptr; cudaGetSymbolAddress((void**)&xdbl,   g_xdbl);
    float* delta  = nullptr; cudaGetSymbolAddress((void**)&delta,  g_delta);
    unsigned short* a1 = nullptr; cudaGetSymbolAddress((void**)&a1, g_a1);
    unsigned short* b1 = nullptr; cudaGetSymbolAddress((void**)&b1, g_b1);
    unsigned short* a2 = nullptr; cudaGetSymbolAddress((void**)&a2, g_a2);
    unsigned short* b2 = nullptr; cudaGetSymbolAddress((void**)&b2, g_b2);

    cudaFuncSetAttribute(gemm_bf16_split,
                         cudaFuncAttributeMaxDynamicSharedMemorySize, GEMM_SMEM_BYTES);

    // 0) split-bf16 conversions for GEMM1 (A: [hi|hi|lo], B: [hi|lo|hi])
    {
        int tot4 = (ML * DM) / 4;
        split_bf16_kernel<<<(tot4 + 255)/256, 256>>>(hidden, a1, DM, tot4, 0);
        tot4 = ((2*DI) * DM) / 4;
        split_bf16_kernel<<<(tot4 + 255)/256, 256>>>(in_proj_w, b1, DM, tot4, 1);
    }
    // 1) xz = hidden @ in_proj_w^T  (HMMA split-bf16, K2 = 3*1024)
    gemm_bf16_split<<<dim3((2*DI)/128, ML/128), 128, GEMM_SMEM_BYTES>>>(
        a1, b1, xz, 2*DI, 3*DM);
    // 2) depthwise conv + silu
    conv_silu_kernel<<<dim3(DI/256, SEQL, BSZ), 256>>>(conv_w, conv_b);
    // 3) Aneg = -exp(A_log)
    prep_A_kernel<<<(DI*DS + 255)/256, 256>>>(A_log);
    // 4) x_dbl = xconv @ x_proj_w^T  (split-K x8 + atomics)
    cudaMemsetAsync(xdbl, 0, (size_t)ML * XD * sizeof(float));
    gemm_xdbl_splitk<<<dim3(ML/32, 8), 256>>>(x_proj_w);
    // 5) delta = softplus(x_dbl[:, :64] @ dt_proj_w^T + b)
    sgemm_tn<<<dim3(DI/BN, ML/BM), 256>>>(xdbl, XD, dt_proj_w, RNK,
                                          delta, DI, ML, DI, RNK, dt_proj_b, 1);
    // 6) chunked selective scan (scanC fuses the GEMM2 A-operand split)
    scanA_kernel<<<BSZ*NCH*(DI/256), 256>>>();
    scanB_kernel<<<BSZ*DS*(DI/256), 256>>>();
    scanC_kernel<<<dim3(DI/256, SEQL, BSZ), 256>>>(Dp);
    // 7) split-bf16 conversion for GEMM2 B operand
    {
        int tot4 = (DM * DI) / 4;
        split_bf16_kernel<<<(tot4 + 255)/256, 256>>>(out_proj_w, b2, DI, tot4, 1);
    }
    // 8) out = yfinal @ out_proj_w^T  (HMMA split-bf16, K2 = 3*2048)
    gemm_bf16_split<<<dim3(DM/128, ML/128), 128, GEMM_SMEM_BYTES>>>(
        a2, b2, out, DM, 3*DI);
}